// round 3
// baseline (speedup 1.0000x reference)
#include <cuda_runtime.h>
#include <math.h>

#define Bx 8
#define Nx 512
#define Dx 128
#define Hx 64
#define FNx 3
#define NLx 3
#define OUTC 10
#define BN (Bx*Nx)

// ---------------- device scratch (static, no allocation) ----------------
__device__ float g_kap[BN];
__device__ float g_f[FNx][BN];
__device__ float g_m1;
__device__ float g_deg[BN];
__device__ float g_u1[FNx][BN];
__device__ float g_gamma[FNx][BN];
__device__ float g_df[FNx][BN];
__device__ float g_fdf[FNx][BN];
__device__ float g_rowloss[BN];
__device__ float g_loss;
__device__ float g_keep1[BN];
__device__ float g_keep2[BN];
__device__ float g_agg[BN*Dx];
__device__ float g_h[NLx][BN*Hx];

// ---------------- kernel 1: curvature MLP + 3 f-MLPs per node ----------------
// grid = BN blocks, 256 threads (4 MLPs x 64 hidden units)
__global__ void node_mlps_kernel(const float* __restrict__ X,
    const float* __restrict__ cW1, const float* __restrict__ cb1,
    const float* __restrict__ cW2, const float* __restrict__ cb2,
    const float* __restrict__ fW1, const float* __restrict__ fb1,
    const float* __restrict__ fW2, const float* __restrict__ fb2)
{
    __shared__ float sx[Dx];
    __shared__ float wsum[8];
    int node = blockIdx.x;
    int tid = threadIdx.x;
    int m = tid >> 6;          // 0 = curv, 1..3 = fn
    int t = tid & 63;
    if (tid < Dx) sx[tid] = X[(size_t)node*Dx + tid];
    __syncthreads();
    const float* W1 = (m==0) ? cW1 : fW1 + (size_t)(m-1)*Dx*Hx;
    const float* b1 = (m==0) ? cb1 : fb1 + (m-1)*Hx;
    const float* W2 = (m==0) ? cW2 : fW2 + (m-1)*Hx;
    float b2 = (m==0) ? cb2[0] : fb2[m-1];
    float acc = b1[t];
    #pragma unroll 8
    for (int d=0; d<Dx; d++) acc += sx[d]*W1[d*Hx + t];
    acc = fmaxf(acc, 0.f);
    float prod = acc * W2[t];
    #pragma unroll
    for (int o=16;o>0;o>>=1) prod += __shfl_xor_sync(0xffffffffu, prod, o);
    if ((tid & 31)==0) wsum[tid>>5] = prod;
    __syncthreads();
    if (t==0) {
        float s = wsum[2*m] + wsum[2*m+1] + b2;
        float sig = 1.f/(1.f + expf(-s));
        if (m==0) g_kap[node] = sig; else g_f[m-1][node] = sig;
    }
}

// ---------------- kernel 2: scalar m1 = sigmoid-MLP(1) ----------------
__global__ void m1_kernel(const float* __restrict__ W1, const float* __restrict__ b1,
                          const float* __restrict__ W2, const float* __restrict__ b2,
                          const float* __restrict__ W3, const float* __restrict__ b3)
{
    __shared__ float x1[64], x2[32];
    int t = threadIdx.x;
    x1[t] = fmaxf(W1[t] + b1[t], 0.f);
    __syncthreads();
    if (t < 32) {
        float a = b2[t];
        #pragma unroll
        for (int i=0;i<64;i++) a += x1[i]*W2[i*32+t];
        x2[t] = fmaxf(a, 0.f);
    }
    __syncthreads();
    if (t==0) {
        float s = b3[0];
        #pragma unroll
        for (int i=0;i<32;i++) s += x2[i]*W3[i];
        g_m1 = 1.f/(1.f+expf(-s));
    }
}

// ---------------- kernel 3: top-k prune masks (exact jax tie semantics) ----------------
// grid = B blocks, N threads; bitonic sort (ascending) then threshold + tie rank
__global__ void prune_kernel(const int* __restrict__ p_ptr)
{
    __shared__ float sv[Nx];
    __shared__ float so[Nx];
    int b = blockIdx.x, t = threadIdx.x;
    float v = g_kap[b*Nx + t];
    so[t] = v; sv[t] = v;
    __syncthreads();
    for (int k=2;k<=Nx;k<<=1){
      for (int j=k>>1;j>0;j>>=1){
        int ixj = t ^ j;
        if (ixj > t){
          float a = sv[t], c = sv[ixj];
          bool up = ((t & k)==0);
          if ((a > c) == up){ sv[t]=c; sv[ixj]=a; }
        }
        __syncthreads();
      }
    }
    int p = *p_ptr;
    float keepA = 1.f, keepB = 1.f;
    for (int phase=0; phase<2; phase++){
        int k = (Nx * p * (phase+1)) / 100;
        bool removed = false;
        if (k >= 1) {
            float T = sv[Nx-k];
            int isgt = (so[t] > T) ? 1 : 0;
            int cgt = __syncthreads_count(isgt);
            int need = k - cgt;
            removed = (so[t] > T);
            if (!removed && so[t]==T && need>0){
                int r=0;
                for (int j=0;j<t;j++) if (so[j]==T) r++;
                if (r < need) removed = true;
            }
        }
        if (phase==0) keepA = removed?0.f:1.f; else keepB = removed?0.f:1.f;
        __syncthreads();
    }
    g_keep1[b*Nx+t] = keepA;
    g_keep2[b*Nx+t] = keepA*keepB;
}

// ---------------- kernel 4: curvature pass 1 (deg, A@f, A@f^2 -> gamma, delta_f) ----
// grid (Nx/8, Bx), 256 threads = 8 warps, warp per row
__global__ void curv_pass1_kernel(const float* __restrict__ A)
{
    __shared__ float sf[FNx][Nx];
    int b = blockIdx.y;
    int tid = threadIdx.x;
    for (int i = tid; i < FNx*Nx; i += 256)
        sf[i/Nx][i%Nx] = g_f[i/Nx][b*Nx + (i%Nx)];
    __syncthreads();
    int w = tid >> 5, lane = tid & 31;
    int row = blockIdx.x*8 + w;
    const float* Ar = A + ((size_t)(b*Nx+row))*Nx;
    float deg=0.f, u1[FNx]={0.f,0.f,0.f}, u2[FNx]={0.f,0.f,0.f};
    for (int j=lane;j<Nx;j+=32){
        float a = Ar[j];
        deg += a;
        #pragma unroll
        for (int i=0;i<FNx;i++){ float fv = sf[i][j]; u1[i]+=a*fv; u2[i]+=a*fv*fv; }
    }
    #pragma unroll
    for (int o=16;o>0;o>>=1){
        deg += __shfl_xor_sync(0xffffffffu,deg,o);
        #pragma unroll
        for (int i=0;i<FNx;i++){
            u1[i] += __shfl_xor_sync(0xffffffffu,u1[i],o);
            u2[i] += __shfl_xor_sync(0xffffffffu,u2[i],o);
        }
    }
    if (lane==0){
        float m1 = g_m1;
        int idx = b*Nx+row;
        g_deg[idx]=deg;
        #pragma unroll
        for (int i=0;i<FNx;i++){
            float fr = sf[i][row];
            g_u1[i][idx]=u1[i];
            float gam = 0.5f*m1*(fr*fr*deg - 2.f*fr*u1[i] + u2[i]);
            float df  = m1*(fr*deg - u1[i]);
            g_gamma[i][idx]=gam; g_df[i][idx]=df; g_fdf[i][idx]=fr*df;
        }
    }
}

// ---------------- kernel 5: curvature pass 2 (A@gamma, A@df, A@fdf -> row loss) ----
__global__ void curv_pass2_kernel(const float* __restrict__ A)
{
    __shared__ float sg[FNx][Nx], sd[FNx][Nx], sfd[FNx][Nx];
    int b = blockIdx.y, tid = threadIdx.x;
    for (int i=tid;i<FNx*Nx;i+=256){
        int f=i/Nx, j=i%Nx; int idx=b*Nx+j;
        sg[f][j]=g_gamma[f][idx]; sd[f][j]=g_df[f][idx]; sfd[f][j]=g_fdf[f][idx];
    }
    __syncthreads();
    int w=tid>>5, lane=tid&31;
    int row = blockIdx.x*8+w;
    const float* Ar = A + ((size_t)(b*Nx+row))*Nx;
    float v1[FNx]={0.f,0.f,0.f}, v2[FNx]={0.f,0.f,0.f}, v3[FNx]={0.f,0.f,0.f};
    for (int j=lane;j<Nx;j+=32){
        float a=Ar[j];
        #pragma unroll
        for (int i=0;i<FNx;i++){ v1[i]+=a*sg[i][j]; v2[i]+=a*sd[i][j]; v3[i]+=a*sfd[i][j]; }
    }
    #pragma unroll
    for (int o=16;o>0;o>>=1){
        #pragma unroll
        for (int i=0;i<FNx;i++){
            v1[i]+=__shfl_xor_sync(0xffffffffu,v1[i],o);
            v2[i]+=__shfl_xor_sync(0xffffffffu,v2[i],o);
            v3[i]+=__shfl_xor_sync(0xffffffffu,v3[i],o);
        }
    }
    if (lane==0){
        int idx=b*Nx+row;
        float m1=g_m1, deg=g_deg[idx], kap=g_kap[idx];
        float term=0.f;
        #pragma unroll
        for (int i=0;i<FNx;i++){
            float gam=sg[i][row], df=sd[i][row], fdf=sfd[i][row];
            float fr = g_f[i][idx];
            float u1 = g_u1[i][idx];
            float dgam = m1*(gam*deg - v1[i]);
            float gfd  = 0.5f*m1*(fdf*deg - fr*v2[i] - df*u1 + v3[i]);
            float g2 = 0.5f*dgam - gfd;
            term += fmaxf(kap*gam - g2, 0.f);
        }
        g_rowloss[idx] = term - 3.f*kap;
    }
}

// ---------------- kernel 6: deterministic loss reduction ----------------
__global__ void loss_reduce_kernel(){
    __shared__ float s[512];
    int t=threadIdx.x;
    float a=0.f;
    for (int i=t;i<BN;i+=512) a+=g_rowloss[i];
    s[t]=a; __syncthreads();
    for (int o=256;o>0;o>>=1){ if(t<o) s[t]+=s[t+o]; __syncthreads(); }
    if(t==0) g_loss=s[0];
}

// ---------------- kernel 7: sparse GIN aggregation (ballot over binary A) ----------
// grid (Nx/8, Bx), 256 threads; warp per row; keep==nullptr means no mask
__global__ void spmm_kernel(const float* __restrict__ A,
                            const float* __restrict__ hin, int Din,
                            const float* __restrict__ keep,
                            const float* __restrict__ eps_ptr, int t_idx,
                            float* __restrict__ out)
{
    int b = blockIdx.y;
    int w = threadIdx.x >> 5, lane = threadIdx.x & 31;
    int row = blockIdx.x*8 + w;
    int idx = b*Nx + row;
    const float* Ar = A + (size_t)idx * Nx;
    float acc[4] = {0.f,0.f,0.f,0.f};
    int Q = Din >> 5;
    unsigned full = 0xffffffffu;
    for (int j0=0;j0<Nx;j0+=32){
        float a = Ar[j0+lane];
        float wv = a;
        if (keep) wv *= keep[b*Nx + j0 + lane];
        unsigned m = __ballot_sync(full, wv != 0.f);
        while (m){
            int s = __ffs(m)-1; m &= (m-1);
            float ws = __shfl_sync(full, wv, s);
            const float* hr = hin + (size_t)(b*Nx + j0 + s)*Din;
            #pragma unroll
            for (int q=0;q<4;q++) if (q<Q) acc[q] += ws * hr[lane + 32*q];
        }
    }
    float eps1 = 1.f + eps_ptr[t_idx];
    float kr = keep ? keep[idx] : 1.f;
    const float* hself = hin + (size_t)idx*Din;
    #pragma unroll
    for (int q=0;q<4;q++) if (q<Q)
        out[(size_t)idx*Din + lane + 32*q] = eps1*hself[lane+32*q] + kr*acc[q];
}

// ---------------- kernel 8: GIN 2-layer MLP per node ----------------
// grid = BN blocks, 64 threads
__global__ void gin_mlp_kernel(const float* __restrict__ agg, int Din,
    const float* __restrict__ W1, const float* __restrict__ b1,
    const float* __restrict__ W2, const float* __restrict__ b2,
    float* __restrict__ hout)
{
    __shared__ float sin_[Dx];
    __shared__ float shid[Hx];
    int node = blockIdx.x, t = threadIdx.x;
    for (int d=t; d<Din; d+=64) sin_[d] = agg[(size_t)node*Din + d];
    __syncthreads();
    float a = b1[t];
    #pragma unroll 8
    for (int d=0;d<Din;d++) a += sin_[d]*W1[d*Hx+t];
    shid[t] = fmaxf(a,0.f);
    __syncthreads();
    float o = b2[t];
    #pragma unroll
    for (int i=0;i<Hx;i++) o += shid[i]*W2[i*Hx+t];
    hout[(size_t)node*Hx + t] = fmaxf(o, 0.f);
}

// ---------------- kernel 9: readout (column sums + output matmul + loss write) ------
// grid = B blocks, 320 threads
__global__ void final_kernel(const float* __restrict__ X,
    const float* __restrict__ outW, const float* __restrict__ outb,
    float* __restrict__ dout, int out_size)
{
    __shared__ float S[320];
    int b = blockIdx.x, t = threadIdx.x;
    float a = 0.f;
    if (t < 128){
        for (int n=0;n<Nx;n++) a += X[((size_t)(b*Nx+n))*Dx + t];
    } else {
        int layer = (t-128)>>6; int c = (t-128)&63;
        for (int n=0;n<Nx;n++) a += g_h[layer][(b*Nx+n)*Hx + c];
    }
    S[t]=a;
    __syncthreads();
    if (t < OUTC){
        float o = outb[t];
        for (int f=0;f<320;f++) o += S[f]*outW[f*OUTC + t];
        dout[b*OUTC + t] = o;
    }
    if (b==0 && t==0 && out_size > Bx*OUTC) dout[Bx*OUTC] = g_loss;
}

// ---------------- launch ----------------
extern "C" void kernel_launch(void* const* d_in, const int* in_sizes, int n_in,
                              void* d_out, int out_size) {
    const float* X    = (const float*)d_in[0];
    const float* A    = (const float*)d_in[1];
    const int*   p    = (const int*)  d_in[2];
    const float* cW1  = (const float*)d_in[3];
    const float* cb1  = (const float*)d_in[4];
    const float* cW2  = (const float*)d_in[5];
    const float* cb2  = (const float*)d_in[6];
    const float* wmW1 = (const float*)d_in[7];
    const float* wmb1 = (const float*)d_in[8];
    const float* wmW2 = (const float*)d_in[9];
    const float* wmb2 = (const float*)d_in[10];
    const float* wmW3 = (const float*)d_in[11];
    const float* wmb3 = (const float*)d_in[12];
    const float* fW1  = (const float*)d_in[13];
    const float* fb1  = (const float*)d_in[14];
    const float* fW2  = (const float*)d_in[15];
    const float* fb2  = (const float*)d_in[16];
    const float* eps  = (const float*)d_in[17];
    const float* g0W1 = (const float*)d_in[18];
    const float* g0b1 = (const float*)d_in[19];
    const float* g0W2 = (const float*)d_in[20];
    const float* g0b2 = (const float*)d_in[21];
    const float* g1W1 = (const float*)d_in[22];
    const float* g1b1 = (const float*)d_in[23];
    const float* g1W2 = (const float*)d_in[24];
    const float* g1b2 = (const float*)d_in[25];
    const float* g2W1 = (const float*)d_in[26];
    const float* g2b1 = (const float*)d_in[27];
    const float* g2W2 = (const float*)d_in[28];
    const float* g2b2 = (const float*)d_in[29];
    const float* outW = (const float*)d_in[30];
    const float* outb = (const float*)d_in[31];
    float* dout = (float*)d_out;

    float *agg_p, *h0_p, *h1_p, *h2_p, *k1_p, *k2_p;
    cudaGetSymbolAddress((void**)&agg_p, g_agg);
    cudaGetSymbolAddress((void**)&h0_p,  g_h);
    h1_p = h0_p + BN*Hx;
    h2_p = h0_p + 2*BN*Hx;
    cudaGetSymbolAddress((void**)&k1_p, g_keep1);
    cudaGetSymbolAddress((void**)&k2_p, g_keep2);

    dim3 gRows(Nx/8, Bx);

    node_mlps_kernel<<<BN,256>>>(X,cW1,cb1,cW2,cb2,fW1,fb1,fW2,fb2);
    m1_kernel<<<1,64>>>(wmW1,wmb1,wmW2,wmb2,wmW3,wmb3);
    prune_kernel<<<Bx,Nx>>>(p);
    curv_pass1_kernel<<<gRows,256>>>(A);
    curv_pass2_kernel<<<gRows,256>>>(A);
    loss_reduce_kernel<<<1,512>>>();

    // GIN layer 0: hin = X (Din=128), no mask
    spmm_kernel<<<gRows,256>>>(A, X, Dx, nullptr, eps, 0, agg_p);
    gin_mlp_kernel<<<BN,64>>>(agg_p, Dx, g0W1, g0b1, g0W2, g0b2, h0_p);
    // GIN layer 1: hin = h0 (Din=64), mask keep1
    spmm_kernel<<<gRows,256>>>(A, h0_p, Hx, k1_p, eps, 1, agg_p);
    gin_mlp_kernel<<<BN,64>>>(agg_p, Hx, g1W1, g1b1, g1W2, g1b2, h1_p);
    // GIN layer 2: hin = h1 (Din=64), mask keep2
    spmm_kernel<<<gRows,256>>>(A, h1_p, Hx, k2_p, eps, 2, agg_p);
    gin_mlp_kernel<<<BN,64>>>(agg_p, Hx, g2W1, g2b1, g2W2, g2b2, h2_p);

    final_kernel<<<Bx,320>>>(X, outW, outb, dout, out_size);
}